// round 2
// baseline (speedup 1.0000x reference)
#include <cuda_runtime.h>
#include <cuda_bf16.h>
#include <cstdint>

// Problem dims
static constexpr int MROWS = 8192;   // B*S
static constexpr int DIN   = 4096;
static constexpr int DOUT  = 4096;

// GEMM tiling
static constexpr int BM = 128, BN = 128, BK = 64;
static constexpr int KTILES = DIN / BK;          // 64
static constexpr int STAGES = 3;
static constexpr int TILE_BYTES  = BM * BK * 2;  // 16384 per operand
static constexpr int STAGE_BYTES = 2 * TILE_BYTES;
static constexpr int SMEM_TOTAL  = STAGES * STAGE_BYTES;  // 98304

// Quantized operands (device globals: no cudaMalloc allowed)
__device__ __nv_bfloat16 g_xq[(size_t)MROWS * DIN];  // 64 MB
__device__ __nv_bfloat16 g_wq[(size_t)DOUT * DIN];   // 32 MB

// ---------- helpers (base-sm_103-safe PTX only) ----------
__device__ __forceinline__ uint32_t smem_u32(const void* p) {
    uint32_t a;
    asm("{ .reg .u64 t; cvta.to.shared.u64 t, %1; cvt.u32.u64 %0, t; }"
        : "=r"(a) : "l"(p));
    return a;
}
// SW128: rows are 128B; XOR 16B-chunk index with row%8 -> conflict-free ldmatrix
__device__ __forceinline__ uint32_t swz(uint32_t o) { return o ^ ((o >> 3) & 0x70); }

__device__ __forceinline__ void cpasync16(uint32_t s, const void* g) {
    asm volatile("cp.async.cg.shared.global [%0], [%1], 16;" :: "r"(s), "l"(g));
}
__device__ __forceinline__ void cp_commit() {
    asm volatile("cp.async.commit_group;" ::: "memory");
}
__device__ __forceinline__ void cp_wait1() {
    asm volatile("cp.async.wait_group 1;" ::: "memory");
}
__device__ __forceinline__ void ldmx4(uint32_t* r, uint32_t addr) {
    asm volatile("ldmatrix.sync.aligned.m8n8.x4.shared.b16 {%0,%1,%2,%3}, [%4];"
                 : "=r"(r[0]), "=r"(r[1]), "=r"(r[2]), "=r"(r[3]) : "r"(addr));
}
__device__ __forceinline__ void mma16816(float* d, const uint32_t* a, const uint32_t* b) {
    asm volatile(
        "mma.sync.aligned.m16n8k16.row.col.f32.bf16.bf16.f32 "
        "{%0,%1,%2,%3}, {%4,%5,%6,%7}, {%8,%9}, {%0,%1,%2,%3};"
        : "+f"(d[0]), "+f"(d[1]), "+f"(d[2]), "+f"(d[3])
        : "r"(a[0]), "r"(a[1]), "r"(a[2]), "r"(a[3]), "r"(b[0]), "r"(b[1]));
}

// ---------- quantization passes ----------
// x_int = trunc(x * input_scale)  (toward zero == astype(int32))
__global__ void __launch_bounds__(256) quant_x_kernel(
    const float* __restrict__ x, const float* __restrict__ iscale) {
    size_t i = ((size_t)blockIdx.x * blockDim.x + threadIdx.x) * 4;
    float is = iscale[0];
    float4 v = *reinterpret_cast<const float4*>(x + i);
    __nv_bfloat162 p0 = __floats2bfloat162_rn(truncf(v.x * is), truncf(v.y * is));
    __nv_bfloat162 p1 = __floats2bfloat162_rn(truncf(v.z * is), truncf(v.w * is));
    uint2 u;
    u.x = *reinterpret_cast<uint32_t*>(&p0);
    u.y = *reinterpret_cast<uint32_t*>(&p1);
    *reinterpret_cast<uint2*>(g_xq + i) = u;
}

// w_int = int8-wraparound(round_half_even(w * weight_scale[row]))
__global__ void __launch_bounds__(256) quant_w_kernel(
    const float* __restrict__ w, const float* __restrict__ wscale) {
    size_t i = ((size_t)blockIdx.x * blockDim.x + threadIdx.x) * 4;
    int row = (int)(i >> 12);  // / DIN
    float ws = wscale[row];
    float4 v = *reinterpret_cast<const float4*>(w + i);
    float f0 = (float)(int8_t)__float2int_rn(v.x * ws);
    float f1 = (float)(int8_t)__float2int_rn(v.y * ws);
    float f2 = (float)(int8_t)__float2int_rn(v.z * ws);
    float f3 = (float)(int8_t)__float2int_rn(v.w * ws);
    __nv_bfloat162 p0 = __floats2bfloat162_rn(f0, f1);
    __nv_bfloat162 p1 = __floats2bfloat162_rn(f2, f3);
    uint2 u;
    u.x = *reinterpret_cast<uint32_t*>(&p0);
    u.y = *reinterpret_cast<uint32_t*>(&p1);
    *reinterpret_cast<uint2*>(g_wq + i) = u;
}

// ---------- GEMM: out = (Xq @ Wq^T) * sc + bias * sc ----------
__global__ void __launch_bounds__(256) gemm_kernel(
    const float* __restrict__ bias, const float* __restrict__ wscale,
    const float* __restrict__ iscale, float* __restrict__ out) {
    extern __shared__ char smem[];
    const uint32_t sbase = smem_u32(smem);
    const int tid  = threadIdx.x;
    const int lane = tid & 31;
    const int warp = tid >> 5;
    const int wm = (warp >> 2) * 64;   // warp M offset within CTA tile
    const int wn = (warp & 3) * 32;    // warp N offset
    const int m0 = blockIdx.y * BM;
    const int n0 = blockIdx.x * BN;

    const __nv_bfloat16* Abase = g_xq + (size_t)m0 * DIN;
    const __nv_bfloat16* Bbase = g_wq + (size_t)n0 * DIN;

    // loader mapping: 1024 16B chunks per operand tile / 256 threads = 4 each
    const int lrow0 = tid >> 3;        // row for u-loop stride of 32 rows
    const int lcol  = (tid & 7) * 8;   // bf16 col (8 elems = 16B)

    auto load_tile = [&](int kt, int stage) {
        const __nv_bfloat16* Ak = Abase + kt * BK;
        const __nv_bfloat16* Bk = Bbase + kt * BK;
        const uint32_t sA = sbase + stage * STAGE_BYTES;
        const uint32_t sB = sA + TILE_BYTES;
#pragma unroll
        for (int u = 0; u < 4; u++) {
            const int row = lrow0 + u * 32;
            const uint32_t so = swz((uint32_t)(row * 128 + lcol * 2));
            cpasync16(sA + so, Ak + (size_t)row * DIN + lcol);
            cpasync16(sB + so, Bk + (size_t)row * DIN + lcol);
        }
    };

    // prologue: prefetch tiles 0 and 1
    load_tile(0, 0); cp_commit();
    load_tile(1, 1); cp_commit();

    float acc[4][4][4];
#pragma unroll
    for (int a = 0; a < 4; a++)
#pragma unroll
        for (int b = 0; b < 4; b++)
#pragma unroll
            for (int c = 0; c < 4; c++) acc[a][b][c] = 0.f;

    const int g = lane >> 3, r = lane & 7;   // ldmatrix address groups

    for (int kt = 0; kt < KTILES; kt++) {
        cp_wait1();
        __syncthreads();
        const int buf = kt % STAGES;
        const uint32_t sA = sbase + buf * STAGE_BYTES;
        const uint32_t sB = sA + TILE_BYTES;

#pragma unroll
        for (int ks = 0; ks < BK / 16; ks++) {
            const int kb = ks * 16;
            uint32_t afrag[4][4];
#pragma unroll
            for (int mi = 0; mi < 4; mi++) {
                // groups: g0 rows m..m+7 @kb | g1 rows m+8..15 @kb | g2 rows m..7 @kb+8 | g3 rows m+8..15 @kb+8
                const int row = wm + mi * 16 + r + ((g & 1) ? 8 : 0);
                const int col = kb + ((g & 2) ? 8 : 0);
                ldmx4(afrag[mi], sA + swz((uint32_t)(row * 128 + col * 2)));
            }
            uint32_t bfrag[4][2];
#pragma unroll
            for (int nb = 0; nb < 2; nb++) {
                // groups: g0 n..n+7 @kb | g1 n..n+7 @kb+8 | g2 n+8..15 @kb | g3 n+8..15 @kb+8
                const int row = wn + nb * 16 + r + ((g & 2) ? 8 : 0);
                const int col = kb + ((g & 1) ? 8 : 0);
                uint32_t t[4];
                ldmx4(t, sB + swz((uint32_t)(row * 128 + col * 2)));
                bfrag[nb * 2 + 0][0] = t[0]; bfrag[nb * 2 + 0][1] = t[1];
                bfrag[nb * 2 + 1][0] = t[2]; bfrag[nb * 2 + 1][1] = t[3];
            }
#pragma unroll
            for (int mi = 0; mi < 4; mi++)
#pragma unroll
                for (int ni = 0; ni < 4; ni++)
                    mma16816(acc[mi][ni], afrag[mi], bfrag[ni]);
        }
        __syncthreads();
        if (kt + STAGES - 1 < KTILES) load_tile(kt + STAGES - 1, (kt + STAGES - 1) % STAGES);
        cp_commit();  // always commit (possibly empty) to keep group accounting uniform
    }

    // epilogue: dequant + bias, write f32
    const float is = iscale[0];
    float sc[4][2], bq[4][2];
#pragma unroll
    for (int ni = 0; ni < 4; ni++)
#pragma unroll
        for (int j = 0; j < 2; j++) {
            const int n = n0 + wn + ni * 8 + (lane & 3) * 2 + j;
            const float s = 1.0f / (wscale[n] * is);
            sc[ni][j] = s;
            bq[ni][j] = bias[n] * s;
        }
    const int mrow = m0 + wm + (lane >> 2);
    const int ncol0 = n0 + wn + (lane & 3) * 2;
#pragma unroll
    for (int mi = 0; mi < 4; mi++) {
#pragma unroll
        for (int ni = 0; ni < 4; ni++) {
            float* o0 = out + (size_t)(mrow + mi * 16) * DOUT + ncol0 + ni * 8;
            float* o1 = o0 + 8 * DOUT;
            float2 v0, v1;
            v0.x = acc[mi][ni][0] * sc[ni][0] + bq[ni][0];
            v0.y = acc[mi][ni][1] * sc[ni][1] + bq[ni][1];
            v1.x = acc[mi][ni][2] * sc[ni][0] + bq[ni][0];
            v1.y = acc[mi][ni][3] * sc[ni][1] + bq[ni][1];
            *reinterpret_cast<float2*>(o0) = v0;
            *reinterpret_cast<float2*>(o1) = v1;
        }
    }
}

// ---------- launch ----------
extern "C" void kernel_launch(void* const* d_in, const int* in_sizes, int n_in,
                              void* d_out, int out_size) {
    const float* x  = (const float*)d_in[0];
    const float* w  = (const float*)d_in[1];
    const float* bi = (const float*)d_in[2];
    const float* ws = (const float*)d_in[3];
    const float* is = (const float*)d_in[4];
    float* out = (float*)d_out;

    cudaFuncSetAttribute(gemm_kernel,
                         cudaFuncAttributeMaxDynamicSharedMemorySize, SMEM_TOTAL);

    quant_x_kernel<<<(MROWS * DIN) / (256 * 4), 256>>>(x, is);
    quant_w_kernel<<<(DOUT * DIN) / (256 * 4), 256>>>(w, ws);
    gemm_kernel<<<dim3(DOUT / BN, MROWS / BM), 256, SMEM_TOTAL>>>(bi, ws, is, out);
}